// round 2
// baseline (speedup 1.0000x reference)
#include <cuda_runtime.h>

#define N_DOF 16
#define BATCH 64
#define SEQ 8192
#define CHUNK 64
#define NCHUNK (SEQ/CHUNK)          // 128
#define NSTATE 48
#define BSD ((size_t)BATCH*(size_t)SEQ*(size_t)N_DOF)

#define DTc 0.01f
#define CU_ 2.5e-5f   // (0.5-beta)*dt*dt
#define CV_ 0.005f    // (1-gamma)*dt
#define BU_ 2.5e-5f   // beta*dt*dt
#define BV_ 0.005f    // gamma*dt

// ---------------- scratch (device globals; no runtime allocation) ----------------
__device__ __align__(16) float g_Af[256];
__device__ __align__(16) float g_Av[256];
__device__ __align__(16) float g_Au[256];
__device__ __align__(16) float g_TL[NSTATE*NSTATE];
__device__ __align__(16) float g_e[(NCHUNK-1)*BATCH*NSTATE];
__device__ __align__(16) float g_init[NCHUNK*BATCH*NSTATE];

// ---------------- K0: setup ----------------
__device__ void invert16(const float* A, float* Ainv, double (*aug)[34], int tid)
{
    if (tid < 16) {
        #pragma unroll
        for (int j = 0; j < 16; j++) {
            aug[tid][j]      = (double)A[tid*16 + j];
            aug[tid][16 + j] = (tid == j) ? 1.0 : 0.0;
        }
    }
    __syncthreads();
    for (int k = 0; k < 16; k++) {
        if (tid == k) {
            double p = 1.0 / aug[k][k];
            #pragma unroll
            for (int j = 0; j < 32; j++) aug[k][j] *= p;
        }
        __syncthreads();
        if (tid < 16 && tid != k) {
            double f = aug[tid][k];
            #pragma unroll
            for (int j = 0; j < 32; j++) aug[tid][j] -= f * aug[k][j];
        }
        __syncthreads();
    }
    if (tid < 16) {
        #pragma unroll
        for (int j = 0; j < 16; j++) Ainv[tid*16 + j] = (float)aug[tid][16 + j];
    }
    __syncthreads();
}

__global__ void setup_kernel(const float* __restrict__ F,
                             const float* __restrict__ M,
                             const float* __restrict__ C,
                             const float* __restrict__ K,
                             float* __restrict__ out)
{
    __shared__ double aug[16][34];
    __shared__ float sM[256], sC[256], sK[256], sKe[256];
    __shared__ float sMinv[256], sAf[256], sAv[256], sAu[256];
    __shared__ float sT[NSTATE*NSTATE];
    __shared__ float sT2[NSTATE*NSTATE];

    const int tid = threadIdx.x;

    sM[tid] = M[tid]; sC[tid] = C[tid]; sK[tid] = K[tid];
    __syncthreads();

    // M^{-1}
    invert16(sM, sMinv, aug, tid);

    // K_eff = M + gamma*dt*C + beta*dt*dt*K ; K_eff^{-1} = A_f
    sKe[tid] = sM[tid] + 0.5f*DTc*sC[tid] + 0.25f*DTc*DTc*sK[tid];
    __syncthreads();
    invert16(sKe, sAf, aug, tid);

    // A_v = A_f @ C, A_u = A_f @ K
    {
        int i = tid >> 4, j = tid & 15;
        float sv = 0.f, su = 0.f;
        #pragma unroll
        for (int k = 0; k < 16; k++) {
            sv = fmaf(sAf[i*16 + k], sC[k*16 + j], sv);
            su = fmaf(sAf[i*16 + k], sK[k*16 + j], su);
        }
        sAv[tid] = sv; sAu[tid] = su;
    }
    __syncthreads();

    g_Af[tid] = sAf[tid]; g_Av[tid] = sAv[tid]; g_Au[tid] = sAu[tid];

    // Build T (48x48) by pushing state basis vectors through one step (f = 0)
    if (tid < NSTATE) {
        float u[16], v[16], a[16];
        #pragma unroll
        for (int j = 0; j < 16; j++) {
            u[j] = (tid == j)      ? 1.f : 0.f;
            v[j] = (tid == j + 16) ? 1.f : 0.f;
            a[j] = (tid == j + 32) ? 1.f : 0.f;
        }
        float up[16], vp[16], an[16];
        #pragma unroll
        for (int i = 0; i < 16; i++) {
            up[i] = fmaf(CU_, a[i], fmaf(DTc, v[i], u[i]));
            vp[i] = fmaf(CV_, a[i], v[i]);
        }
        #pragma unroll
        for (int i = 0; i < 16; i++) {
            float s = 0.f;
            #pragma unroll
            for (int j = 0; j < 16; j++)
                s = fmaf(sAv[i*16 + j], vp[j], fmaf(sAu[i*16 + j], up[j], s));
            an[i] = -s;
        }
        #pragma unroll
        for (int i = 0; i < 16; i++) {
            sT[(i)     *NSTATE + tid] = fmaf(BU_, an[i], up[i]);
            sT[(16 + i)*NSTATE + tid] = fmaf(BV_, an[i], vp[i]);
            sT[(32 + i)*NSTATE + tid] = an[i];
        }
    }
    __syncthreads();

    // TL = T^64 via 6 squarings (ping-pong)
    float* Asq = sT;
    float* Bsq = sT2;
    for (int it = 0; it < 6; it++) {
        for (int e = tid; e < NSTATE*NSTATE; e += 256) {
            int r = e / NSTATE, cc = e % NSTATE;
            float s = 0.f;
            #pragma unroll
            for (int k2 = 0; k2 < NSTATE; k2++)
                s = fmaf(Asq[r*NSTATE + k2], Asq[k2*NSTATE + cc], s);
            Bsq[e] = s;
        }
        __syncthreads();
        float* t = Asq; Asq = Bsq; Bsq = t;
    }
    for (int e = tid; e < NSTATE*NSTATE; e += 256) g_TL[e] = Asq[e];

    // a0 = Minv @ F[b,0,:], write init_0 and t=0 output row
    for (int idx = tid; idx < BATCH*16; idx += 256) {
        int b = idx >> 4, i = idx & 15;
        const float* f0p = F + (size_t)b * SEQ * N_DOF;
        float s = 0.f;
        #pragma unroll
        for (int j = 0; j < 16; j++) s = fmaf(sMinv[i*16 + j], f0p[j], s);
        float* ip = g_init + (size_t)b * NSTATE;
        ip[i] = 0.f; ip[16 + i] = 0.f; ip[32 + i] = s;
        size_t o = ((size_t)b * SEQ) * N_DOF + i;
        out[o] = 0.f; out[BSD + o] = 0.f; out[2*BSD + o] = s;
    }
}

// ---------------- K1 / K3: chunked scans ----------------
__device__ __forceinline__ float dot4(float acc, float4 m, float4 val)
{
    acc = fmaf(m.x, val.x, acc);
    acc = fmaf(m.y, val.y, acc);
    acc = fmaf(m.z, val.z, acc);
    acc = fmaf(m.w, val.w, acc);
    return acc;
}

template<bool FINAL>
__global__ void __launch_bounds__(256, 2) scan_kernel(const float* __restrict__ F,
                                                      float* __restrict__ out)
{
    const int tid  = threadIdx.x;
    const int lane = tid & 15;
    const int unit = blockIdx.x * 16 + (tid >> 4);
    const int b    = unit & (BATCH - 1);
    const int c    = unit >> 6;

    // matrix rows held in registers (row = lane's output DOF)
    const float4* Afr = reinterpret_cast<const float4*>(g_Af + lane*16);
    const float4* Avr = reinterpret_cast<const float4*>(g_Av + lane*16);
    const float4* Aur = reinterpret_cast<const float4*>(g_Au + lane*16);
    const float4 af0 = Afr[0], af1 = Afr[1], af2 = Afr[2], af3 = Afr[3];
    const float4 av0 = Avr[0], av1 = Avr[1], av2 = Avr[2], av3 = Avr[3];
    const float4 au0 = Aur[0], au1 = Aur[1], au2 = Aur[2], au3 = Aur[3];

    float u, v, a;
    if (FINAL) {
        const float* ip = g_init + ((size_t)c * BATCH + b) * NSTATE;
        u = ip[lane]; v = ip[lane + 16]; a = ip[lane + 32];
    } else {
        u = 0.f; v = 0.f; a = 0.f;
    }

    __shared__ __align__(16) float sh[16][32];   // [unit][u_pred(16) | v_pred(16)]
    float* shu = &sh[tid >> 4][0];
    float* shv = &sh[tid >> 4][16];

    const float* Fb = F + (size_t)b * SEQ * N_DOF;

    #pragma unroll 1
    for (int k = 1; k <= CHUNK; k++) {
        const int t  = c * CHUNK + k;
        const int tc = FINAL ? (t < SEQ ? t : SEQ - 1) : t;
        const float4* fp = reinterpret_cast<const float4*>(Fb + (size_t)tc * N_DOF);
        const float4 f0 = fp[0], f1 = fp[1], f2 = fp[2], f3 = fp[3];

        const float up = fmaf(CU_, a, fmaf(DTc, v, u));
        const float vp = fmaf(CV_, a, v);
        shu[lane] = up; shv[lane] = vp;
        __syncwarp();

        const float4* U4 = reinterpret_cast<const float4*>(shu);
        const float4* V4 = reinterpret_cast<const float4*>(shv);

        float accf = 0.f, accv = 0.f, accu = 0.f;
        accf = dot4(accf, af0, f0);
        accf = dot4(accf, af1, f1);
        accf = dot4(accf, af2, f2);
        accf = dot4(accf, af3, f3);
        {
            float4 xv;
            xv = U4[0]; accu = dot4(accu, au0, xv);
            xv = U4[1]; accu = dot4(accu, au1, xv);
            xv = U4[2]; accu = dot4(accu, au2, xv);
            xv = U4[3]; accu = dot4(accu, au3, xv);
            xv = V4[0]; accv = dot4(accv, av0, xv);
            xv = V4[1]; accv = dot4(accv, av1, xv);
            xv = V4[2]; accv = dot4(accv, av2, xv);
            xv = V4[3]; accv = dot4(accv, av3, xv);
        }
        const float an = accf - accv - accu;
        const float un = fmaf(BU_, an, up);
        const float vn = fmaf(BV_, an, vp);

        if (FINAL && t < SEQ) {
            size_t o = ((size_t)b * SEQ + t) * N_DOF + lane;
            out[o]         = un;
            out[BSD + o]   = vn;
            out[2*BSD + o] = an;
        }
        u = un; v = vn; a = an;
        __syncwarp();
    }

    if (!FINAL) {
        float* ep = g_e + ((size_t)c * BATCH + b) * NSTATE;
        ep[lane] = u; ep[lane + 16] = v; ep[lane + 32] = a;
    }
}

// ---------------- K2: sequential chunk chain (per batch) ----------------
__global__ void chain_kernel()
{
    const int b = blockIdx.x;
    const int i = threadIdx.x;        // 0..47
    __shared__ float cur[NSTATE];

    float tl[NSTATE];
    #pragma unroll
    for (int j = 0; j < NSTATE; j++) tl[j] = g_TL[i*NSTATE + j];

    cur[i] = g_init[(size_t)b * NSTATE + i];
    __syncthreads();

    for (int c = 1; c < NCHUNK; c++) {
        const float ev = g_e[((size_t)(c - 1) * BATCH + b) * NSTATE + i];
        float a0 = 0.f, a1 = 0.f, a2 = 0.f, a3 = 0.f;
        #pragma unroll
        for (int j = 0; j < NSTATE; j += 4) {
            a0 = fmaf(tl[j],     cur[j],     a0);
            a1 = fmaf(tl[j + 1], cur[j + 1], a1);
            a2 = fmaf(tl[j + 2], cur[j + 2], a2);
            a3 = fmaf(tl[j + 3], cur[j + 3], a3);
        }
        const float r = (a0 + a1) + (a2 + a3) + ev;
        g_init[((size_t)c * BATCH + b) * NSTATE + i] = r;
        __syncthreads();
        cur[i] = r;
        __syncthreads();
    }
}

// ---------------- launch ----------------
extern "C" void kernel_launch(void* const* d_in, const int* in_sizes, int n_in,
                              void* d_out, int out_size)
{
    const float* F = (const float*)d_in[0];
    const float* M = (const float*)d_in[1];
    const float* C = (const float*)d_in[2];
    const float* K = (const float*)d_in[3];
    float* out = (float*)d_out;

    setup_kernel<<<1, 256>>>(F, M, C, K, out);

    // K1: zero-init local scans for chunks 0..126 (127*64 units / 16 per block)
    scan_kernel<false><<<(NCHUNK - 1) * BATCH / 16, 256>>>(F, nullptr);

    // K2: sequential combine across chunks, independent per batch
    chain_kernel<<<BATCH, NSTATE>>>();

    // K3: final scans from correct initial states, all 128 chunks
    scan_kernel<true><<<NCHUNK * BATCH / 16, 256>>>(F, out);
}